// round 4
// baseline (speedup 1.0000x reference)
#include <cuda_runtime.h>
#include <cstdint>

// Problem constants (GCNLayer_12317966205308)
#define NN 50000
#define EE 800000
#define D  64

// Scratch: __device__ globals (allocation inside kernel_launch is forbidden).
// 256B-aligned: accessed via float4 (16B) loads/stores.
__device__ __align__(256) float g_xws[NN * D];   // dis[j] * (x[j] @ W)
__device__ __align__(256) float g_acc[NN * D];   // accumulator (init = self-loop term)
__device__ __align__(256) float g_dis[NN];       // rsqrt(deg)
__device__ __align__(256) int   g_deg[NN];

// ---------------------------------------------------------------------------
// K1: deg init = 1 (self loop)
__global__ void k_deg_init(int n) {
    int i = blockIdx.x * blockDim.x + threadIdx.x;
    if (i < n) g_deg[i] = 1;
}

// K2: deg count over edge targets. Edge index is int32 (JAX demotes int64).
__global__ void k_deg_count(const int* __restrict__ ei, int E, int n) {
    int e = blockIdx.x * blockDim.x + threadIdx.x;
    if (e >= E) return;
    int dst = ei[E + e];
    if ((unsigned)dst < (unsigned)n) atomicAdd(&g_deg[dst], 1);
}

// K3: xws = dis * (x @ W); acc = xws (self-loop contribution); store dis.
// 256 threads/block, 4 rows/block. W (16 KB) staged in smem.
__global__ void k_xw(const float* __restrict__ x, const float* __restrict__ W, int n) {
    __shared__ float Ws[D * D];
    __shared__ float xs[4][D];
    int tid = threadIdx.x;

    #pragma unroll
    for (int i = tid; i < D * D; i += 256) Ws[i] = W[i];

    int row0 = blockIdx.x * 4;
    int r = tid >> 6;        // 0..3
    int c = tid & 63;        // 0..63
    int node = row0 + r;
    xs[r][c] = (node < n) ? x[node * D + c] : 0.0f;
    __syncthreads();

    if (node < n) {
        float s = 0.0f;
        #pragma unroll
        for (int k = 0; k < D; k++) s = fmaf(xs[r][k], Ws[k * D + c], s);
        float dis = rsqrtf((float)g_deg[node]);   // deg >= 1 always
        float v = dis * s;
        g_xws[node * D + c] = v;
        g_acc[node * D + c] = v;                  // self-loop: dis[i]*xw[i]
        if (c == 0) g_dis[node] = dis;
    }
}

// K4: edge scatter. 16 threads per edge; each loads one float4 of xws[src]
// and issues 4 scalar atomicAdds (REDG.ADD.F32) into acc[dst].
__global__ void k_scatter(const int* __restrict__ ei, int E, int n) {
    int t = blockIdx.x * blockDim.x + threadIdx.x;
    int e = t >> 4;
    int lane = t & 15;
    if (e >= E) return;
    int src = ei[e];
    int dst = ei[E + e];
    if ((unsigned)src >= (unsigned)n || (unsigned)dst >= (unsigned)n) return;
    float4 v = reinterpret_cast<const float4*>(g_xws + src * D)[lane];
    float* ap = g_acc + dst * D + lane * 4;
    atomicAdd(ap + 0, v.x);
    atomicAdd(ap + 1, v.y);
    atomicAdd(ap + 2, v.z);
    atomicAdd(ap + 3, v.w);
}

// K5: out = relu(dis * acc + b), float4 vectorized
__global__ void k_final(const float* __restrict__ b, float* __restrict__ out, int n) {
    int t = blockIdx.x * blockDim.x + threadIdx.x;
    if (t >= n * (D / 4)) return;
    int node = t >> 4;
    int c4 = t & 15;
    float dis = g_dis[node];
    float4 a = reinterpret_cast<const float4*>(g_acc)[t];
    float4 bb = reinterpret_cast<const float4*>(b)[c4];
    float4 o;
    o.x = fmaxf(fmaf(dis, a.x, bb.x), 0.0f);
    o.y = fmaxf(fmaf(dis, a.y, bb.y), 0.0f);
    o.z = fmaxf(fmaf(dis, a.z, bb.z), 0.0f);
    o.w = fmaxf(fmaf(dis, a.w, bb.w), 0.0f);
    reinterpret_cast<float4*>(out)[t] = o;
}

// ---------------------------------------------------------------------------
extern "C" void kernel_launch(void* const* d_in, const int* in_sizes, int n_in,
                              void* d_out, int out_size) {
    const float* x  = (const float*)d_in[0];   // [N, 64] f32
    const int*   ei = (const int*)d_in[1];     // [2, E] int32 (JAX x64 disabled)
    const float* W  = (const float*)d_in[2];   // [64, 64] f32
    const float* b  = (const float*)d_in[3];   // [64] f32
    float* out = (float*)d_out;

    int N = in_sizes[0] / D;
    int E = in_sizes[1] / 2;

    k_deg_init<<<(N + 255) / 256, 256>>>(N);
    k_deg_count<<<(E + 255) / 256, 256>>>(ei, E, N);
    k_xw<<<(N + 3) / 4, 256>>>(x, W, N);
    {
        long long work = (long long)E * 16;
        k_scatter<<<(int)((work + 255) / 256), 256>>>(ei, E, N);
    }
    {
        int work = N * (D / 4);
        k_final<<<(work + 255) / 256, 256>>>(b, out, N);
    }
}

// round 5
// speedup vs baseline: 2.3199x; 2.3199x over previous
#include <cuda_runtime.h>
#include <cstdint>

// Problem constants (GCNLayer_12317966205308)
#define NN 50000
#define EE 800000
#define D  64

__device__ __align__(256) float g_xws[NN * D];   // dis[j] * (x[j] @ W)
__device__ __align__(256) float g_acc[NN * D];   // accumulator (init = self-loop term)
__device__ __align__(256) float g_dis[NN];       // rsqrt(deg)
__device__ __align__(256) int   g_deg[NN];

// ---------------------------------------------------------------------------
// K1: deg init = 1 (self loop)
__global__ void k_deg_init(int n) {
    int i = blockIdx.x * blockDim.x + threadIdx.x;
    if (i < n) g_deg[i] = 1;
}

// K2: deg count over edge targets (edge index is int32)
__global__ void k_deg_count(const int* __restrict__ ei, int E) {
    int e = blockIdx.x * blockDim.x + threadIdx.x;
    if (e < E) atomicAdd(&g_deg[ei[E + e]], 1);
}

// K3: xws = dis * (x @ W); acc = xws (self-loop term); store dis.
// 256 threads/block, 64 rows/block. Thread computes a 4-row x 4-col tile.
// W staged once per block (12.5 MB total L2 W-traffic vs 200 MB before).
__global__ void __launch_bounds__(256) k_xw(const float* __restrict__ x,
                                            const float* __restrict__ W, int n) {
    __shared__ float Ws[D * D];        // [k][c]
    __shared__ float xs[64][D + 1];    // [r][k], padded
    int tid = threadIdx.x;
    int row0 = blockIdx.x * 64;

    // Stage W: 4096 floats = 1024 float4, 4 per thread
    {
        const float4* W4 = (const float4*)W;
        float4* Ws4 = (float4*)Ws;
        #pragma unroll
        for (int i = 0; i < 4; i++) Ws4[tid + 256 * i] = W4[tid + 256 * i];
    }
    // Stage x rows row0..row0+63: 1024 float4, 4 per thread
    #pragma unroll
    for (int i = 0; i < 4; i++) {
        int f = tid + 256 * i;
        int r = f >> 4, c4 = f & 15;
        int node = row0 + r;
        float4 v = (node < n) ? ((const float4*)(x + (size_t)node * D))[c4]
                              : make_float4(0.f, 0.f, 0.f, 0.f);
        xs[r][c4 * 4 + 0] = v.x; xs[r][c4 * 4 + 1] = v.y;
        xs[r][c4 * 4 + 2] = v.z; xs[r][c4 * 4 + 3] = v.w;
    }
    __syncthreads();

    int cg = tid & 15;   // cols [cg*4, cg*4+4)
    int rg = tid >> 4;   // rows [rg*4, rg*4+4)
    float acc[4][4] = {};
    #pragma unroll 4
    for (int k = 0; k < D; k++) {
        float4 w = *(const float4*)&Ws[k * D + cg * 4];
        #pragma unroll
        for (int rr = 0; rr < 4; rr++) {
            float xv = xs[rg * 4 + rr][k];
            acc[rr][0] = fmaf(xv, w.x, acc[rr][0]);
            acc[rr][1] = fmaf(xv, w.y, acc[rr][1]);
            acc[rr][2] = fmaf(xv, w.z, acc[rr][2]);
            acc[rr][3] = fmaf(xv, w.w, acc[rr][3]);
        }
    }

    #pragma unroll
    for (int rr = 0; rr < 4; rr++) {
        int node = row0 + rg * 4 + rr;
        if (node < n) {
            float dis = rsqrtf((float)g_deg[node]);   // deg >= 1 always
            float4 v = make_float4(dis * acc[rr][0], dis * acc[rr][1],
                                   dis * acc[rr][2], dis * acc[rr][3]);
            ((float4*)(g_xws + (size_t)node * D))[cg] = v;
            ((float4*)(g_acc + (size_t)node * D))[cg] = v;
            if (cg == 0) g_dis[node] = dis;
        }
    }
}

// K4: edge scatter. 16 threads/edge; one LDG.128 gather + one RED.128
// (red.global.add.v4.f32, PTX ISA 8.1 / sm_90+). The R2 trap on this
// instruction was garbage addresses from the int64 cast, not the RED itself.
__global__ void k_scatter(const int* __restrict__ ei, int E) {
    int t = blockIdx.x * blockDim.x + threadIdx.x;
    int e = t >> 4;
    int lane = t & 15;
    if (e >= E) return;
    int src = ei[e];
    int dst = ei[E + e];
    float4 v = reinterpret_cast<const float4*>(g_xws + (size_t)src * D)[lane];
    float* ap = g_acc + (size_t)dst * D + lane * 4;
    asm volatile("red.global.add.v4.f32 [%0], {%1, %2, %3, %4};"
                 :: "l"(ap), "f"(v.x), "f"(v.y), "f"(v.z), "f"(v.w)
                 : "memory");
}

// K5: out = relu(dis * acc + b), float4 vectorized
__global__ void k_final(const float* __restrict__ b, float* __restrict__ out, int n) {
    int t = blockIdx.x * blockDim.x + threadIdx.x;
    if (t >= n * (D / 4)) return;
    int node = t >> 4;
    int c4 = t & 15;
    float dis = g_dis[node];
    float4 a = reinterpret_cast<const float4*>(g_acc)[t];
    float4 bb = reinterpret_cast<const float4*>(b)[c4];
    float4 o;
    o.x = fmaxf(fmaf(dis, a.x, bb.x), 0.0f);
    o.y = fmaxf(fmaf(dis, a.y, bb.y), 0.0f);
    o.z = fmaxf(fmaf(dis, a.z, bb.z), 0.0f);
    o.w = fmaxf(fmaf(dis, a.w, bb.w), 0.0f);
    reinterpret_cast<float4*>(out)[t] = o;
}

// ---------------------------------------------------------------------------
extern "C" void kernel_launch(void* const* d_in, const int* in_sizes, int n_in,
                              void* d_out, int out_size) {
    const float* x  = (const float*)d_in[0];   // [N, 64] f32
    const int*   ei = (const int*)d_in[1];     // [2, E] int32
    const float* W  = (const float*)d_in[2];   // [64, 64] f32
    const float* b  = (const float*)d_in[3];   // [64] f32
    float* out = (float*)d_out;

    int N = in_sizes[0] / D;
    int E = in_sizes[1] / 2;

    k_deg_init<<<(N + 255) / 256, 256>>>(N);
    k_deg_count<<<(E + 255) / 256, 256>>>(ei, E);
    k_xw<<<(N + 63) / 64, 256>>>(x, W, N);
    {
        long long work = (long long)E * 16;
        k_scatter<<<(int)((work + 255) / 256), 256>>>(ei, E);
    }
    {
        int work = N * (D / 4);
        k_final<<<(work + 255) / 256, 256>>>(b, out, N);
    }
}

// round 6
// speedup vs baseline: 2.4351x; 1.0496x over previous
#include <cuda_runtime.h>
#include <cstdint>

// Problem constants (GCNLayer_12317966205308)
#define NN 50000
#define EE 800000
#define D  64

__device__ __align__(256) float g_xws[NN * D];   // dis[j] * (x[j] @ W)
__device__ __align__(256) float g_acc[NN * D];   // accumulator (init = self-loop term)
__device__ __align__(256) float g_dis[NN];       // rsqrt(deg)
__device__ __align__(256) int   g_deg[NN];

// ---------------------------------------------------------------------------
// K1: deg init = 1 (self loop)
__global__ void k_deg_init(int n) {
    int i = blockIdx.x * blockDim.x + threadIdx.x;
    if (i < n) g_deg[i] = 1;
}

// K2: deg count over edge targets, 4 edges/thread via int4
__global__ void k_deg_count(const int* __restrict__ ei, int E) {
    int q = blockIdx.x * blockDim.x + threadIdx.x;
    int e0 = q * 4;
    if (e0 + 4 <= E) {
        int4 d = *reinterpret_cast<const int4*>(ei + E + e0);   // E % 4 == 0
        atomicAdd(&g_deg[d.x], 1);
        atomicAdd(&g_deg[d.y], 1);
        atomicAdd(&g_deg[d.z], 1);
        atomicAdd(&g_deg[d.w], 1);
    } else {
        for (int e = e0; e < E; e++) atomicAdd(&g_deg[ei[E + e]], 1);
    }
}

// K3: xws = dis * (x @ W); acc = xws (self-loop term); store dis.
// 256 threads/block, 64 rows/block. Thread computes a 4-row x 4-col tile.
__global__ void __launch_bounds__(256) k_xw(const float* __restrict__ x,
                                            const float* __restrict__ W, int n) {
    __shared__ float Ws[D * D];        // [k][c]
    __shared__ float xs[64][D + 1];    // [r][k], padded
    int tid = threadIdx.x;
    int row0 = blockIdx.x * 64;

    {
        const float4* W4 = (const float4*)W;
        float4* Ws4 = (float4*)Ws;
        #pragma unroll
        for (int i = 0; i < 4; i++) Ws4[tid + 256 * i] = W4[tid + 256 * i];
    }
    #pragma unroll
    for (int i = 0; i < 4; i++) {
        int f = tid + 256 * i;
        int r = f >> 4, c4 = f & 15;
        int node = row0 + r;
        float4 v = (node < n) ? ((const float4*)(x + (size_t)node * D))[c4]
                              : make_float4(0.f, 0.f, 0.f, 0.f);
        xs[r][c4 * 4 + 0] = v.x; xs[r][c4 * 4 + 1] = v.y;
        xs[r][c4 * 4 + 2] = v.z; xs[r][c4 * 4 + 3] = v.w;
    }
    __syncthreads();

    int cg = tid & 15;   // cols [cg*4, cg*4+4)
    int rg = tid >> 4;   // rows [rg*4, rg*4+4)
    float acc[4][4] = {};
    #pragma unroll 4
    for (int k = 0; k < D; k++) {
        float4 w = *(const float4*)&Ws[k * D + cg * 4];
        #pragma unroll
        for (int rr = 0; rr < 4; rr++) {
            float xv = xs[rg * 4 + rr][k];
            acc[rr][0] = fmaf(xv, w.x, acc[rr][0]);
            acc[rr][1] = fmaf(xv, w.y, acc[rr][1]);
            acc[rr][2] = fmaf(xv, w.z, acc[rr][2]);
            acc[rr][3] = fmaf(xv, w.w, acc[rr][3]);
        }
    }

    #pragma unroll
    for (int rr = 0; rr < 4; rr++) {
        int node = row0 + rg * 4 + rr;
        if (node < n) {
            float dis = rsqrtf((float)g_deg[node]);   // deg >= 1 always
            float4 v = make_float4(dis * acc[rr][0], dis * acc[rr][1],
                                   dis * acc[rr][2], dis * acc[rr][3]);
            ((float4*)(g_xws + (size_t)node * D))[cg] = v;
            ((float4*)(g_acc + (size_t)node * D))[cg] = v;
            if (cg == 0) g_dis[node] = dis;
        }
    }
}

__device__ __forceinline__ void red4(float* ap, float4 v) {
    asm volatile("red.global.add.v4.f32 [%0], {%1, %2, %3, %4};"
                 :: "l"(ap), "f"(v.x), "f"(v.y), "f"(v.z), "f"(v.w)
                 : "memory");
}

// K4: edge scatter. 16 threads x 4 edges per thread-quad: batch index loads
// (int4), then 4 independent gathers (MLP=4), then 4 vector REDs.
__global__ void k_scatter(const int* __restrict__ ei, int E) {
    int t = blockIdx.x * blockDim.x + threadIdx.x;
    int lane = t & 15;
    int q = t >> 4;
    int e0 = q * 4;
    if (e0 >= E) return;

    if (e0 + 4 <= E) {   // fast path; E % 4 == 0 so int4 loads are aligned
        int4 s = *reinterpret_cast<const int4*>(ei + e0);
        int4 d = *reinterpret_cast<const int4*>(ei + E + e0);
        float4 v0 = reinterpret_cast<const float4*>(g_xws + (size_t)s.x * D)[lane];
        float4 v1 = reinterpret_cast<const float4*>(g_xws + (size_t)s.y * D)[lane];
        float4 v2 = reinterpret_cast<const float4*>(g_xws + (size_t)s.z * D)[lane];
        float4 v3 = reinterpret_cast<const float4*>(g_xws + (size_t)s.w * D)[lane];
        red4(g_acc + (size_t)d.x * D + lane * 4, v0);
        red4(g_acc + (size_t)d.y * D + lane * 4, v1);
        red4(g_acc + (size_t)d.z * D + lane * 4, v2);
        red4(g_acc + (size_t)d.w * D + lane * 4, v3);
    } else {
        for (int e = e0; e < E; e++) {
            int src = ei[e], dst = ei[E + e];
            float4 v = reinterpret_cast<const float4*>(g_xws + (size_t)src * D)[lane];
            red4(g_acc + (size_t)dst * D + lane * 4, v);
        }
    }
}

// K5: out = relu(dis * acc + b), float4 vectorized
__global__ void k_final(const float* __restrict__ b, float* __restrict__ out, int n) {
    int t = blockIdx.x * blockDim.x + threadIdx.x;
    if (t >= n * (D / 4)) return;
    int node = t >> 4;
    int c4 = t & 15;
    float dis = g_dis[node];
    float4 a = reinterpret_cast<const float4*>(g_acc)[t];
    float4 bb = reinterpret_cast<const float4*>(b)[c4];
    float4 o;
    o.x = fmaxf(fmaf(dis, a.x, bb.x), 0.0f);
    o.y = fmaxf(fmaf(dis, a.y, bb.y), 0.0f);
    o.z = fmaxf(fmaf(dis, a.z, bb.z), 0.0f);
    o.w = fmaxf(fmaf(dis, a.w, bb.w), 0.0f);
    reinterpret_cast<float4*>(out)[t] = o;
}

// ---------------------------------------------------------------------------
extern "C" void kernel_launch(void* const* d_in, const int* in_sizes, int n_in,
                              void* d_out, int out_size) {
    const float* x  = (const float*)d_in[0];   // [N, 64] f32
    const int*   ei = (const int*)d_in[1];     // [2, E] int32
    const float* W  = (const float*)d_in[2];   // [64, 64] f32
    const float* b  = (const float*)d_in[3];   // [64] f32
    float* out = (float*)d_out;

    int N = in_sizes[0] / D;
    int E = in_sizes[1] / 2;

    k_deg_init<<<(N + 255) / 256, 256>>>(N);
    {
        int quads = (E + 3) / 4;
        k_deg_count<<<(quads + 255) / 256, 256>>>(ei, E);
    }
    k_xw<<<(N + 63) / 64, 256>>>(x, W, N);
    {
        long long work = ((long long)E + 3) / 4 * 16;
        k_scatter<<<(int)((work + 255) / 256), 256>>>(ei, E);
    }
    {
        int work = N * (D / 4);
        k_final<<<(work + 255) / 256, 256>>>(b, out, N);
    }
}